// round 3
// baseline (speedup 1.0000x reference)
#include <cuda_runtime.h>
#include <cstdint>
#include <cstddef>

#define N_NODES 50000
#define N_EDGES 800000
#define SCAN_TILE 512
#define N_TILES ((N_NODES + SCAN_TILE - 1) / SCAN_TILE)   // 98

// ---------------- scratch ----------------
__device__ int   g_deg[N_NODES];
__device__ float g_norm[N_NODES];
__device__ int   g_rowstart[N_NODES + 1];
__device__ int   g_fill[N_NODES];
__device__ int   g_tilesum[128];
__device__ int   g_tileoff[128];
__device__ int   g_csr[N_EDGES];
__device__ float g_t1[N_NODES * 128];
__device__ float g_t2[N_NODES * 128];
__device__ float g_h1[N_NODES * 64];
__device__ float g_h2[N_NODES * 64];

// ---------------- CSR build ----------------
__global__ void zero_deg_kernel() {
    int i = blockIdx.x * blockDim.x + threadIdx.x;
    if (i < N_NODES) g_deg[i] = 0;
}

__global__ void hist_kernel(const int* __restrict__ dst) {
    int i = blockIdx.x * blockDim.x + threadIdx.x;
    if (i < N_EDGES) atomicAdd(&g_deg[dst[i]], 1);
}

__global__ void scan_tiles_kernel() {
    __shared__ int sh[SCAN_TILE];
    int t = threadIdx.x;
    int i = blockIdx.x * SCAN_TILE + t;
    int v = (i < N_NODES) ? g_deg[i] : 0;
    sh[t] = v;
    __syncthreads();
    #pragma unroll
    for (int off = 1; off < SCAN_TILE; off <<= 1) {
        int x = (t >= off) ? sh[t - off] : 0;
        __syncthreads();
        sh[t] += x;
        __syncthreads();
    }
    if (i < N_NODES) g_rowstart[i] = sh[t] - v;       // exclusive within tile
    if (t == SCAN_TILE - 1) g_tilesum[blockIdx.x] = sh[t];
}

__global__ void scan_sums_kernel() {
    __shared__ int sh[128];
    int t = threadIdx.x;
    int v = (t < N_TILES) ? g_tilesum[t] : 0;
    sh[t] = v;
    __syncthreads();
    #pragma unroll
    for (int off = 1; off < 128; off <<= 1) {
        int x = (t >= off) ? sh[t - off] : 0;
        __syncthreads();
        sh[t] += x;
        __syncthreads();
    }
    if (t < N_TILES) g_tileoff[t] = sh[t] - v;        // exclusive
    if (t == 127) g_rowstart[N_NODES] = sh[127];
}

__global__ void finalize_kernel() {
    int i = blockIdx.x * blockDim.x + threadIdx.x;
    if (i < N_NODES) {
        int rs = g_rowstart[i] + g_tileoff[i >> 9];
        g_rowstart[i] = rs;
        g_fill[i] = rs;
        float d = (float)g_deg[i];
        g_norm[i] = rsqrtf(d < 1.0f ? 1.0f : d);
    }
}

__global__ void fill_kernel(const int* __restrict__ src, const int* __restrict__ dst) {
    int i = blockIdx.x * blockDim.x + threadIdx.x;
    if (i < N_EDGES) {
        int p = atomicAdd(&g_fill[dst[i]], 1);
        g_csr[p] = src[i];
    }
}

// ---------------- propagation: out[n] = norm[n] * sum_{e in in(n)} X[src_e]*norm[src_e] ----------------
// F=128: 1 node/warp, lane owns float4. F=64: 2 nodes/warp, 16 lanes each own float4.
template <int F>
__global__ void prop_kernel(const float* __restrict__ X,
                            float* __restrict__ out) {
    int gwarp = (blockIdx.x * blockDim.x + threadIdx.x) >> 5;
    int lane = threadIdx.x & 31;
    int node, sub;
    if constexpr (F == 128) { node = gwarp;                  sub = lane;      }
    else                    { node = gwarp * 2 + (lane >> 4); sub = lane & 15; }
    if (node >= N_NODES) return;

    int beg = g_rowstart[node];
    int end = g_rowstart[node + 1];

    float4 acc = make_float4(0.f, 0.f, 0.f, 0.f);

    int e = beg;
    for (; e + 8 <= end; e += 8) {
        int s[8];
        #pragma unroll
        for (int j = 0; j < 8; j++) s[j] = g_csr[e + j];
        float nn[8];
        #pragma unroll
        for (int j = 0; j < 8; j++) nn[j] = g_norm[s[j]];
        float4 a[8];
        #pragma unroll
        for (int j = 0; j < 8; j++)
            a[j] = *(const float4*)(X + (size_t)s[j] * F + sub * 4);
        #pragma unroll
        for (int j = 0; j < 8; j++) {
            acc.x += a[j].x * nn[j];
            acc.y += a[j].y * nn[j];
            acc.z += a[j].z * nn[j];
            acc.w += a[j].w * nn[j];
        }
    }
    for (; e < end; e++) {
        int s = g_csr[e];
        float ns = g_norm[s];
        float4 a = *(const float4*)(X + (size_t)s * F + sub * 4);
        acc.x += a.x * ns; acc.y += a.y * ns; acc.z += a.z * ns; acc.w += a.w * ns;
    }

    float m = g_norm[node];
    size_t base = (size_t)node * F + sub * 4;
    float4 r;
    r.x = m * acc.x; r.y = m * acc.y; r.z = m * acc.z; r.w = m * acc.w;
    *(float4*)(out + base) = r;
}

// ---------------- tf32 tensor-core GEMM with folded Chebyshev weights ----------------
// out = bias + X@(W0-W2) + U1@(-W1) + U2@(2*W2)
// Block: 256 threads (8 warps), 256 rows. W staged in smem (tf32 bits, padded) per segment.

__device__ __forceinline__ uint32_t f2tf32(float f) {
    uint32_t r;
    asm("cvt.rna.tf32.f32 %0, %1;" : "=r"(r) : "f"(f));
    return r;
}

__device__ __forceinline__ void mma_tf32(float* c, const uint32_t* a, uint32_t b0, uint32_t b1) {
    asm volatile(
        "mma.sync.aligned.m16n8k8.row.col.f32.tf32.tf32.f32 "
        "{%0,%1,%2,%3}, {%4,%5,%6,%7}, {%8,%9}, {%0,%1,%2,%3};"
        : "+f"(c[0]), "+f"(c[1]), "+f"(c[2]), "+f"(c[3])
        : "r"(a[0]), "r"(a[1]), "r"(a[2]), "r"(a[3]), "r"(b0), "r"(b1));
}

template <int F, int FOUT>
__global__ void gemm3_mma_kernel(const float* __restrict__ X0,
                                 const float* __restrict__ X1,
                                 const float* __restrict__ X2,
                                 const float* __restrict__ W,
                                 const float* __restrict__ bias,
                                 float* __restrict__ out) {
    constexpr int NT  = FOUT / 8;        // n-tiles: 8 (FOUT=64) or 5 (FOUT=40)
    constexpr int LDW = FOUT + 1;        // padded smem stride (conflict-free)
    __shared__ uint32_t Ws[F * LDW];

    int tid  = threadIdx.x;
    int warp = tid >> 5;
    int lane = tid & 31;
    int grp  = lane >> 2;                // 0..7  (A rows / B cols)
    int qid  = lane & 3;                 // 0..3  (k within fragment)
    int r0 = blockIdx.x * 256 + warp * 32;

    float c[2][NT][4];
    #pragma unroll
    for (int t = 0; t < 2; t++)
        #pragma unroll
        for (int n = 0; n < NT; n++)
            #pragma unroll
            for (int j = 0; j < 4; j++) c[t][n][j] = 0.f;

    const float* segs[3] = {X0, X1, X2};

    // clamped row pointers (offsets applied per segment)
    int ra0 = r0 + grp;       if (ra0 >= N_NODES) ra0 = N_NODES - 1;
    int ra1 = r0 + grp + 8;   if (ra1 >= N_NODES) ra1 = N_NODES - 1;
    int ra2 = r0 + grp + 16;  if (ra2 >= N_NODES) ra2 = N_NODES - 1;
    int ra3 = r0 + grp + 24;  if (ra3 >= N_NODES) ra3 = N_NODES - 1;

    #pragma unroll
    for (int seg = 0; seg < 3; ++seg) {
        // ---- stage folded, tf32-converted weights into smem ----
        __syncthreads();
        for (int i = tid; i < F * FOUT; i += 256) {
            int k = i / FOUT, col = i - k * FOUT;
            float v;
            if (seg == 0)      v = W[i] - W[2 * F * FOUT + i];      // W0 - W2
            else if (seg == 1) v = -W[F * FOUT + i];                // -W1
            else               v = 2.0f * W[2 * F * FOUT + i];      // 2*W2
            Ws[k * LDW + col] = f2tf32(v);
        }
        __syncthreads();

        const float* X = segs[seg];
        const float* p0 = X + (size_t)ra0 * F;
        const float* p1 = X + (size_t)ra1 * F;
        const float* p2 = X + (size_t)ra2 * F;
        const float* p3 = X + (size_t)ra3 * F;

        for (int k0 = 0; k0 < F; k0 += 8) {
            uint32_t A0[4], A1[4];
            A0[0] = f2tf32(p0[k0 + qid]);
            A0[1] = f2tf32(p1[k0 + qid]);
            A0[2] = f2tf32(p0[k0 + qid + 4]);
            A0[3] = f2tf32(p1[k0 + qid + 4]);
            A1[0] = f2tf32(p2[k0 + qid]);
            A1[1] = f2tf32(p3[k0 + qid]);
            A1[2] = f2tf32(p2[k0 + qid + 4]);
            A1[3] = f2tf32(p3[k0 + qid + 4]);

            const uint32_t* w0 = Ws + (k0 + qid) * LDW + grp;
            const uint32_t* w1 = Ws + (k0 + qid + 4) * LDW + grp;
            #pragma unroll
            for (int n = 0; n < NT; n++) {
                uint32_t b0 = w0[n * 8];
                uint32_t b1 = w1[n * 8];
                mma_tf32(c[0][n], A0, b0, b1);
                mma_tf32(c[1][n], A1, b0, b1);
            }
        }
    }

    // epilogue
    #pragma unroll
    for (int t = 0; t < 2; t++) {
        int rA = r0 + t * 16 + grp;
        int rB = rA + 8;
        #pragma unroll
        for (int n = 0; n < NT; n++) {
            int col = n * 8 + qid * 2;
            float bx = bias[col], by = bias[col + 1];
            if (rA < N_NODES) {
                float2 v = make_float2(c[t][n][0] + bx, c[t][n][1] + by);
                *(float2*)(out + (size_t)rA * FOUT + col) = v;
            }
            if (rB < N_NODES) {
                float2 v = make_float2(c[t][n][2] + bx, c[t][n][3] + by);
                *(float2*)(out + (size_t)rB * FOUT + col) = v;
            }
        }
    }
}

// ---------------- host ----------------
extern "C" void kernel_launch(void* const* d_in, const int* in_sizes, int n_in,
                              void* d_out, int out_size) {
    const float* features = (const float*)d_in[0];   // [50000,128]
    const int*   src      = (const int*)d_in[1];     // [800000]
    const int*   dst      = (const int*)d_in[2];     // [800000]
    const float* W1       = (const float*)d_in[3];   // [384,64]
    const float* b1       = (const float*)d_in[4];   // [64]
    const float* W2       = (const float*)d_in[5];   // [192,64]
    const float* b2       = (const float*)d_in[6];   // [64]
    const float* W3       = (const float*)d_in[7];   // [192,40]
    const float* b3       = (const float*)d_in[8];   // [40]
    float* out            = (float*)d_out;           // [50000,40]

    float *t1, *t2, *h1, *h2;
    cudaGetSymbolAddress((void**)&t1, g_t1);
    cudaGetSymbolAddress((void**)&t2, g_t2);
    cudaGetSymbolAddress((void**)&h1, g_h1);
    cudaGetSymbolAddress((void**)&h2, g_h2);

    // ---- CSR build (dst-bucketed) ----
    zero_deg_kernel<<<(N_NODES + 255) / 256, 256>>>();
    hist_kernel<<<(N_EDGES + 255) / 256, 256>>>(dst);
    scan_tiles_kernel<<<N_TILES, SCAN_TILE>>>();
    scan_sums_kernel<<<1, 128>>>();
    finalize_kernel<<<(N_NODES + 255) / 256, 256>>>();
    fill_kernel<<<(N_EDGES + 255) / 256, 256>>>(src, dst);

    const int PROP_BLK = 256;  // 8 warps
    const int GRID128 = (N_NODES + 7) / 8;            // 1 node/warp
    const int GRID64  = (N_NODES / 2 + 7) / 8;        // 2 nodes/warp
    const int GEMM_GRID = (N_NODES + 255) / 256;

    // U1 = P@X, U2 = P@U1; gemm applies folded weights:
    //   out = X@(W0-W2) + U1@(-W1) + U2@(2*W2) + b

    // ---- Layer 1: F=128 -> 64 ----
    prop_kernel<128><<<GRID128, PROP_BLK>>>(features, t1);
    prop_kernel<128><<<GRID128, PROP_BLK>>>(t1, t2);
    gemm3_mma_kernel<128, 64><<<GEMM_GRID, 256>>>(features, t1, t2, W1, b1, h1);

    // ---- Layer 2: F=64 -> 64 ----
    prop_kernel<64><<<GRID64, PROP_BLK>>>(h1, t1);
    prop_kernel<64><<<GRID64, PROP_BLK>>>(t1, t2);
    gemm3_mma_kernel<64, 64><<<GEMM_GRID, 256>>>(h1, t1, t2, W2, b2, h2);

    // ---- Layer 3: F=64 -> 40 ----
    prop_kernel<64><<<GRID64, PROP_BLK>>>(h2, t1);
    prop_kernel<64><<<GRID64, PROP_BLK>>>(t1, t2);
    gemm3_mma_kernel<64, 40><<<GEMM_GRID, 256>>>(h2, t1, t2, W3, b3, out);
}

// round 6
// speedup vs baseline: 1.2241x; 1.2241x over previous
#include <cuda_runtime.h>
#include <cuda_fp16.h>
#include <cstdint>
#include <cstddef>

#define N_NODES 50000
#define N_EDGES 800000
#define SCAN_TILE 512
#define N_TILES ((N_NODES + SCAN_TILE - 1) / SCAN_TILE)   // 98

// ---------------- scratch ----------------
__device__ int    g_deg[N_NODES];
__device__ float  g_norm[N_NODES];
__device__ int    g_rowstart[N_NODES + 1];
__device__ int    g_fill[N_NODES];
__device__ int    g_tilesum[128];
__device__ int    g_tileoff[128];
__device__ int    g_csr[N_EDGES];
__device__ __align__(16) __half g_xh[N_NODES * 128];   // fp16 features
__device__ __align__(16) __half g_t1h[N_NODES * 128];
__device__ __align__(16) __half g_t2h[N_NODES * 128];
__device__ __align__(16) __half g_h1h[N_NODES * 64];
__device__ __align__(16) __half g_h2h[N_NODES * 64];

// ---------------- feature convert ----------------
__global__ void cvt_kernel(const float* __restrict__ X) {
    int i = blockIdx.x * blockDim.x + threadIdx.x;   // over half2 pairs
    if (i < N_NODES * 64) {
        float2 v = ((const float2*)X)[i];
        ((__half2*)g_xh)[i] = __float22half2_rn(v);
    }
}

// ---------------- CSR build ----------------
__global__ void zero_deg_kernel() {
    int i = blockIdx.x * blockDim.x + threadIdx.x;
    if (i < N_NODES) g_deg[i] = 0;
}

__global__ void hist_kernel(const int* __restrict__ dst) {
    int i = blockIdx.x * blockDim.x + threadIdx.x;   // groups of 4
    if (i * 4 + 4 <= N_EDGES) {
        int4 d = ((const int4*)dst)[i];
        atomicAdd(&g_deg[d.x], 1);
        atomicAdd(&g_deg[d.y], 1);
        atomicAdd(&g_deg[d.z], 1);
        atomicAdd(&g_deg[d.w], 1);
    }
}

__global__ void scan_tiles_kernel() {
    __shared__ int sh[SCAN_TILE];
    int t = threadIdx.x;
    int i = blockIdx.x * SCAN_TILE + t;
    int v = (i < N_NODES) ? g_deg[i] : 0;
    sh[t] = v;
    __syncthreads();
    #pragma unroll
    for (int off = 1; off < SCAN_TILE; off <<= 1) {
        int x = (t >= off) ? sh[t - off] : 0;
        __syncthreads();
        sh[t] += x;
        __syncthreads();
    }
    if (i < N_NODES) g_rowstart[i] = sh[t] - v;
    if (t == SCAN_TILE - 1) g_tilesum[blockIdx.x] = sh[t];
}

__global__ void scan_sums_kernel() {
    __shared__ int sh[128];
    int t = threadIdx.x;
    int v = (t < N_TILES) ? g_tilesum[t] : 0;
    sh[t] = v;
    __syncthreads();
    #pragma unroll
    for (int off = 1; off < 128; off <<= 1) {
        int x = (t >= off) ? sh[t - off] : 0;
        __syncthreads();
        sh[t] += x;
        __syncthreads();
    }
    if (t < N_TILES) g_tileoff[t] = sh[t] - v;
    if (t == 127) g_rowstart[N_NODES] = sh[127];
}

__global__ void finalize_kernel() {
    int i = blockIdx.x * blockDim.x + threadIdx.x;
    if (i < N_NODES) {
        int rs = g_rowstart[i] + g_tileoff[i >> 9];
        g_rowstart[i] = rs;
        g_fill[i] = rs;
        float d = (float)g_deg[i];
        g_norm[i] = rsqrtf(d < 1.0f ? 1.0f : d);
    }
}

__global__ void fill_kernel(const int* __restrict__ src, const int* __restrict__ dst) {
    int i = blockIdx.x * blockDim.x + threadIdx.x;
    if (i * 4 + 4 <= N_EDGES) {
        int4 d = ((const int4*)dst)[i];
        int4 s = ((const int4*)src)[i];
        g_csr[atomicAdd(&g_fill[d.x], 1)] = s.x;
        g_csr[atomicAdd(&g_fill[d.y], 1)] = s.y;
        g_csr[atomicAdd(&g_fill[d.z], 1)] = s.z;
        g_csr[atomicAdd(&g_fill[d.w], 1)] = s.w;
    }
}

// ---------------- propagation (fp16 storage, fp32 accumulate) ----------------
// out[n] = norm[n] * sum_{e in in(n)} X[src_e]*norm[src_e]
// F=128: 2 nodes/warp, 16 lanes x uint4 (8 halves) = 128.
// F=64 : 4 nodes/warp,  8 lanes x uint4 (8 halves) = 64.
template <int F>
__global__ void prop_h(const __half* __restrict__ X, __half* __restrict__ out) {
    constexpr int LPN = F / 8;                    // lanes per node: 16 or 8
    int gwarp = (blockIdx.x * blockDim.x + threadIdx.x) >> 5;
    int lane = threadIdx.x & 31;
    int node = gwarp * (32 / LPN) + lane / LPN;
    int sub  = lane % LPN;
    if (node >= N_NODES) return;
    int beg = g_rowstart[node];
    int end = g_rowstart[node + 1];

    float acc[8];
    #pragma unroll
    for (int i = 0; i < 8; i++) acc[i] = 0.f;

    int e = beg;
    for (; e + 8 <= end; e += 8) {
        int s[8];
        #pragma unroll
        for (int j = 0; j < 8; j++) s[j] = g_csr[e + j];
        float nn[8];
        #pragma unroll
        for (int j = 0; j < 8; j++) nn[j] = g_norm[s[j]];
        uint4 v[8];
        #pragma unroll
        for (int j = 0; j < 8; j++)
            v[j] = *(const uint4*)(X + (size_t)s[j] * F + sub * 8);
        #pragma unroll
        for (int j = 0; j < 8; j++) {
            float2 f0 = __half22float2(*(const __half2*)&v[j].x);
            float2 f1 = __half22float2(*(const __half2*)&v[j].y);
            float2 f2 = __half22float2(*(const __half2*)&v[j].z);
            float2 f3 = __half22float2(*(const __half2*)&v[j].w);
            acc[0] += f0.x * nn[j]; acc[1] += f0.y * nn[j];
            acc[2] += f1.x * nn[j]; acc[3] += f1.y * nn[j];
            acc[4] += f2.x * nn[j]; acc[5] += f2.y * nn[j];
            acc[6] += f3.x * nn[j]; acc[7] += f3.y * nn[j];
        }
    }
    for (; e < end; e++) {
        int s = g_csr[e];
        float ns = g_norm[s];
        uint4 v = *(const uint4*)(X + (size_t)s * F + sub * 8);
        float2 f0 = __half22float2(*(const __half2*)&v.x);
        float2 f1 = __half22float2(*(const __half2*)&v.y);
        float2 f2 = __half22float2(*(const __half2*)&v.z);
        float2 f3 = __half22float2(*(const __half2*)&v.w);
        acc[0] += f0.x * ns; acc[1] += f0.y * ns;
        acc[2] += f1.x * ns; acc[3] += f1.y * ns;
        acc[4] += f2.x * ns; acc[5] += f2.y * ns;
        acc[6] += f3.x * ns; acc[7] += f3.y * ns;
    }

    float m = g_norm[node];
    uint4 r;
    *(__half2*)&r.x = __floats2half2_rn(m * acc[0], m * acc[1]);
    *(__half2*)&r.y = __floats2half2_rn(m * acc[2], m * acc[3]);
    *(__half2*)&r.z = __floats2half2_rn(m * acc[4], m * acc[5]);
    *(__half2*)&r.w = __floats2half2_rn(m * acc[6], m * acc[7]);
    *(uint4*)(out + (size_t)node * F + sub * 8) = r;
}

// ---------------- fp16 tensor-core GEMM with folded Chebyshev weights ----------------
// out = bias + X@(W0-W2) + U1@(-W1) + U2@(2*W2),  mma.m16n8k16 f16xf16+f32

__device__ __forceinline__ void mma_f16(float* c, const uint32_t* a, uint32_t b0, uint32_t b1) {
    asm volatile(
        "mma.sync.aligned.m16n8k16.row.col.f32.f16.f16.f32 "
        "{%0,%1,%2,%3}, {%4,%5,%6,%7}, {%8,%9}, {%0,%1,%2,%3};"
        : "+f"(c[0]), "+f"(c[1]), "+f"(c[2]), "+f"(c[3])
        : "r"(a[0]), "r"(a[1]), "r"(a[2]), "r"(a[3]), "r"(b0), "r"(b1));
}

template <int F, int FOUT, typename OutT>
__global__ void gemm3_mma_kernel(const __half* __restrict__ X0,
                                 const __half* __restrict__ X1,
                                 const __half* __restrict__ X2,
                                 const float* __restrict__ W,
                                 const float* __restrict__ bias,
                                 OutT* __restrict__ out) {
    constexpr int NT  = FOUT / 8;        // n-tiles: 8 or 5
    constexpr int LDK = F + 2;           // padded k-stride (even)
    __shared__ alignas(16) __half Ws[FOUT * LDK];    // Ws[col][k]

    int tid  = threadIdx.x;
    int warp = tid >> 5;
    int lane = tid & 31;
    int grp  = lane >> 2;                // 0..7
    int qid  = lane & 3;                 // 0..3
    int r0 = blockIdx.x * 256 + warp * 32;

    float c[2][NT][4];
    #pragma unroll
    for (int t = 0; t < 2; t++)
        #pragma unroll
        for (int n = 0; n < NT; n++)
            #pragma unroll
            for (int j = 0; j < 4; j++) c[t][n][j] = 0.f;

    const __half* segs[3] = {X0, X1, X2};

    int ra0 = r0 + grp;       if (ra0 >= N_NODES) ra0 = N_NODES - 1;
    int ra1 = r0 + grp + 8;   if (ra1 >= N_NODES) ra1 = N_NODES - 1;
    int ra2 = r0 + grp + 16;  if (ra2 >= N_NODES) ra2 = N_NODES - 1;
    int ra3 = r0 + grp + 24;  if (ra3 >= N_NODES) ra3 = N_NODES - 1;

    #pragma unroll
    for (int seg = 0; seg < 3; ++seg) {
        __syncthreads();
        for (int i = tid; i < F * FOUT; i += 256) {
            int k = i / FOUT, col = i - k * FOUT;
            float v;
            if (seg == 0)      v = W[i] - W[2 * F * FOUT + i];      // W0 - W2
            else if (seg == 1) v = -W[F * FOUT + i];                // -W1
            else               v = 2.0f * W[2 * F * FOUT + i];      // 2*W2
            Ws[col * LDK + k] = __float2half_rn(v);
        }
        __syncthreads();

        const __half* X  = segs[seg];
        const __half* p0 = X + (size_t)ra0 * F;
        const __half* p1 = X + (size_t)ra1 * F;
        const __half* p2 = X + (size_t)ra2 * F;
        const __half* p3 = X + (size_t)ra3 * F;

        for (int k0 = 0; k0 < F; k0 += 16) {
            int ka = k0 + 2 * qid;
            uint32_t A0[4], A1[4];
            A0[0] = *(const uint32_t*)(p0 + ka);
            A0[1] = *(const uint32_t*)(p1 + ka);
            A0[2] = *(const uint32_t*)(p0 + ka + 8);
            A0[3] = *(const uint32_t*)(p1 + ka + 8);
            A1[0] = *(const uint32_t*)(p2 + ka);
            A1[1] = *(const uint32_t*)(p3 + ka);
            A1[2] = *(const uint32_t*)(p2 + ka + 8);
            A1[3] = *(const uint32_t*)(p3 + ka + 8);

            #pragma unroll
            for (int n = 0; n < NT; n++) {
                const __half* wb = Ws + (n * 8 + grp) * LDK + ka;
                uint32_t b0 = *(const uint32_t*)(wb);
                uint32_t b1 = *(const uint32_t*)(wb + 8);
                mma_f16(c[0][n], A0, b0, b1);
                mma_f16(c[1][n], A1, b0, b1);
            }
        }
    }

    #pragma unroll
    for (int t = 0; t < 2; t++) {
        int rA = r0 + t * 16 + grp;
        int rB = rA + 8;
        #pragma unroll
        for (int n = 0; n < NT; n++) {
            int col = n * 8 + qid * 2;
            float bx = bias[col], by = bias[col + 1];
            if (rA < N_NODES) {
                if constexpr (sizeof(OutT) == 2) {
                    __half2 v = __floats2half2_rn(c[t][n][0] + bx, c[t][n][1] + by);
                    *(__half2*)((__half*)out + (size_t)rA * FOUT + col) = v;
                } else {
                    float2 v = make_float2(c[t][n][0] + bx, c[t][n][1] + by);
                    *(float2*)((float*)out + (size_t)rA * FOUT + col) = v;
                }
            }
            if (rB < N_NODES) {
                if constexpr (sizeof(OutT) == 2) {
                    __half2 v = __floats2half2_rn(c[t][n][2] + bx, c[t][n][3] + by);
                    *(__half2*)((__half*)out + (size_t)rB * FOUT + col) = v;
                } else {
                    float2 v = make_float2(c[t][n][2] + bx, c[t][n][3] + by);
                    *(float2*)((float*)out + (size_t)rB * FOUT + col) = v;
                }
            }
        }
    }
}

// ---------------- host ----------------
extern "C" void kernel_launch(void* const* d_in, const int* in_sizes, int n_in,
                              void* d_out, int out_size) {
    const float* features = (const float*)d_in[0];   // [50000,128]
    const int*   src      = (const int*)d_in[1];     // [800000]
    const int*   dst      = (const int*)d_in[2];     // [800000]
    const float* W1       = (const float*)d_in[3];   // [384,64]
    const float* b1       = (const float*)d_in[4];   // [64]
    const float* W2       = (const float*)d_in[5];   // [192,64]
    const float* b2       = (const float*)d_in[6];   // [64]
    const float* W3       = (const float*)d_in[7];   // [192,40]
    const float* b3       = (const float*)d_in[8];   // [40]
    float* out            = (float*)d_out;           // [50000,40]

    __half *xh, *t1, *t2, *h1, *h2;
    cudaGetSymbolAddress((void**)&xh, g_xh);
    cudaGetSymbolAddress((void**)&t1, g_t1h);
    cudaGetSymbolAddress((void**)&t2, g_t2h);
    cudaGetSymbolAddress((void**)&h1, g_h1h);
    cudaGetSymbolAddress((void**)&h2, g_h2h);

    // ---- feature convert + CSR build ----
    cvt_kernel<<<(N_NODES * 64 + 255) / 256, 256>>>(features);
    zero_deg_kernel<<<(N_NODES + 255) / 256, 256>>>();
    hist_kernel<<<(N_EDGES / 4 + 255) / 256, 256>>>(dst);
    scan_tiles_kernel<<<N_TILES, SCAN_TILE>>>();
    scan_sums_kernel<<<1, 128>>>();
    finalize_kernel<<<(N_NODES + 255) / 256, 256>>>();
    fill_kernel<<<(N_EDGES / 4 + 255) / 256, 256>>>(src, dst);

    const int PROP_BLK = 256;                         // 8 warps
    const int GRID128 = (N_NODES + 15) / 16;          // 2 nodes/warp
    const int GRID64  = (N_NODES + 31) / 32;          // 4 nodes/warp
    const int GEMM_GRID = (N_NODES + 255) / 256;

    // U1 = P@X, U2 = P@U1; out = X@(W0-W2) + U1@(-W1) + U2@(2W2) + b

    // ---- Layer 1: F=128 -> 64 ----
    prop_h<128><<<GRID128, PROP_BLK>>>(xh, t1);
    prop_h<128><<<GRID128, PROP_BLK>>>(t1, t2);
    gemm3_mma_kernel<128, 64, __half><<<GEMM_GRID, 256>>>(xh, t1, t2, W1, b1, h1);

    // ---- Layer 2: F=64 -> 64 ----
    prop_h<64><<<GRID64, PROP_BLK>>>(h1, t1);
    prop_h<64><<<GRID64, PROP_BLK>>>(t1, t2);
    gemm3_mma_kernel<64, 64, __half><<<GEMM_GRID, 256>>>(h1, t1, t2, W2, b2, h2);

    // ---- Layer 3: F=64 -> 40 ----
    prop_h<64><<<GRID64, PROP_BLK>>>(h2, t1);
    prop_h<64><<<GRID64, PROP_BLK>>>(t1, t2);
    gemm3_mma_kernel<64, 40, float><<<GEMM_GRID, 256>>>(h2, t1, t2, W3, b3, out);
}